// round 11
// baseline (speedup 1.0000x reference)
#include <cuda_runtime.h>
#include <cuda_bf16.h>

#define BB 4
#define LL 2048
#define QQ 300
#define DM 256
#define DI 512
#define NH 8
#define HP 64
#define ZXLD 1040

typedef unsigned long long ull;

__device__ float g_ZX [BB*LL*ZXLD];
__device__ float g_Qp [BB*QQ*DI];
__device__ float g_AT [(size_t)BB*LL*NH*640];   // packed (dA0,dA1,dtB0,dtB1) x 160 pairs, lane-major
__device__ float g_C  [BB*LL*320];              // padded to 320
__device__ float g_yf [BB*LL*DI];
__device__ float g_yb [BB*LL*DI];
__device__ float g_Sf [BB*DI*QQ];
__device__ float g_Sb [BB*DI*QQ];
__device__ float g_key[BB*LL*DI];
__device__ float g_ls [BB*QQ*DI];

__device__ __forceinline__ float fexp(float x) {
    x = fminf(fmaxf(x, -80.0f), 80.0f);
    float t = x * 1.4426950408889634f;
    float n = rintf(t);
    float f = t - n;
    float p = 1.3400886e-3f;
    p = fmaf(p, f, 9.6181291e-3f);
    p = fmaf(p, f, 5.5503633e-2f);
    p = fmaf(p, f, 2.4022646e-1f);
    p = fmaf(p, f, 6.9314718e-1f);
    p = fmaf(p, f, 1.0f);
    return p * __int_as_float(((int)n + 127) << 23);
}

__device__ __forceinline__ float flog(float x) {
    int ix = __float_as_int(x);
    int e = ((ix >> 23) & 255) - 127;
    float m = __int_as_float((ix & 0x007fffff) | 0x3f800000);
    if (m > 1.41421356f) { m *= 0.5f; e += 1; }
    float t = m - 1.0f;
    float p = 7.0376836292e-2f;
    p = fmaf(p, t, -1.1514610310e-1f);
    p = fmaf(p, t,  1.1676998740e-1f);
    p = fmaf(p, t, -1.2420140846e-1f);
    p = fmaf(p, t,  1.4249322787e-1f);
    p = fmaf(p, t, -1.6668057665e-1f);
    p = fmaf(p, t,  2.0000714765e-1f);
    p = fmaf(p, t, -2.4999993993e-1f);
    p = fmaf(p, t,  3.3333331174e-1f);
    float t2 = t * t;
    float r = fmaf(t * t2, p, fmaf(-0.5f, t2, t));
    return fmaf((float)e, 0.6931471805599453f, r);
}

__device__ __forceinline__ float fsoftplus(float x) {
    return fmaxf(x, 0.0f) + flog(1.0f + fexp(-fabsf(x)));
}

__device__ __forceinline__ ull pk(float x, float y) {
    ull r; asm("mov.b64 %0,{%1,%2};" : "=l"(r) : "f"(x), "f"(y)); return r;
}
__device__ __forceinline__ float2 upk(ull v) {
    float2 f; asm("mov.b64 {%0,%1},%2;" : "=f"(f.x), "=f"(f.y) : "l"(v)); return f;
}
__device__ __forceinline__ ull ffma2(ull a, ull b, ull c) {
    ull r; asm("fma.rn.f32x2 %0,%1,%2,%3;" : "=l"(r) : "l"(a), "l"(b), "l"(c)); return r;
}
__device__ __forceinline__ ull fmul2(ull a, ull b) {
    ull r; asm("mul.rn.f32x2 %0,%1,%2;" : "=l"(r) : "l"(a), "l"(b)); return r;
}

// C[M,N] = A[M,K] @ W[N,K]^T
__global__ void __launch_bounds__(256) gemm_nt(
    const float* __restrict__ A, const float* __restrict__ W, float* __restrict__ C,
    int M, int N, int K, int lda, int ldc)
{
    __shared__ __align__(16) float As[16][68];
    __shared__ __align__(16) float Ws[16][68];
    int bm = blockIdx.y * 64, bn = blockIdx.x * 64;
    int tid = threadIdx.x;
    int lm = tid >> 2, lk = (tid & 3) << 2;
    int tm = (tid >> 4) << 2, tn = (tid & 15) << 2;
    float acc[4][4];
#pragma unroll
    for (int i = 0; i < 4; i++)
#pragma unroll
        for (int j = 0; j < 4; j++) acc[i][j] = 0.0f;

    for (int k0 = 0; k0 < K; k0 += 16) {
        float4 av = make_float4(0.f,0.f,0.f,0.f);
        if (bm + lm < M) av = *(const float4*)(A + (size_t)(bm+lm)*lda + k0 + lk);
        As[lk+0][lm]=av.x; As[lk+1][lm]=av.y; As[lk+2][lm]=av.z; As[lk+3][lm]=av.w;
        float4 wv = make_float4(0.f,0.f,0.f,0.f);
        if (bn + lm < N) wv = *(const float4*)(W + (size_t)(bn+lm)*K + k0 + lk);
        Ws[lk+0][lm]=wv.x; Ws[lk+1][lm]=wv.y; Ws[lk+2][lm]=wv.z; Ws[lk+3][lm]=wv.w;
        __syncthreads();
#pragma unroll
        for (int kk = 0; kk < 16; kk++) {
            float4 a = *(const float4*)&As[kk][tm];
            float4 b = *(const float4*)&Ws[kk][tn];
            acc[0][0]=fmaf(a.x,b.x,acc[0][0]); acc[0][1]=fmaf(a.x,b.y,acc[0][1]);
            acc[0][2]=fmaf(a.x,b.z,acc[0][2]); acc[0][3]=fmaf(a.x,b.w,acc[0][3]);
            acc[1][0]=fmaf(a.y,b.x,acc[1][0]); acc[1][1]=fmaf(a.y,b.y,acc[1][1]);
            acc[1][2]=fmaf(a.y,b.z,acc[1][2]); acc[1][3]=fmaf(a.y,b.w,acc[1][3]);
            acc[2][0]=fmaf(a.z,b.x,acc[2][0]); acc[2][1]=fmaf(a.z,b.y,acc[2][1]);
            acc[2][2]=fmaf(a.z,b.z,acc[2][2]); acc[2][3]=fmaf(a.z,b.w,acc[2][3]);
            acc[3][0]=fmaf(a.w,b.x,acc[3][0]); acc[3][1]=fmaf(a.w,b.y,acc[3][1]);
            acc[3][2]=fmaf(a.w,b.z,acc[3][2]); acc[3][3]=fmaf(a.w,b.w,acc[3][3]);
        }
        __syncthreads();
    }
#pragma unroll
    for (int i = 0; i < 4; i++) {
        int row = bm + tm + i;
        if (row < M)
#pragma unroll
            for (int j = 0; j < 4; j++) {
                int col = bn + tn + j;
                if (col < N) C[(size_t)row*ldc + col] = acc[i][j];
            }
    }
}

__global__ void __launch_bounds__(320) prepass_kernel(
    const float* __restrict__ dist, const float* __restrict__ ZX,
    const float* __restrict__ W_bc, const float* __restrict__ W_dt,
    const float* __restrict__ dt_bias, const float* __restrict__ A_log,
    float* __restrict__ gAT, float* __restrict__ gC)
{
    int bl = blockIdx.x;
    int tid = threadIdx.x;
    __shared__ float sWbc[32], sWdt[128], sA[8], sdtb[8], sdtpb[8], sbb, scb;
    if (tid < 32) sWbc[tid] = W_bc[tid];
    else if (tid < 160) sWdt[tid-32] = W_dt[tid-32];
    else if (tid < 168) {
        int h = tid - 160;
        sA[h] = -fexp(A_log[h]);
        sdtb[h] = dt_bias[h];
        sdtpb[h] = ZX[(size_t)bl*ZXLD + 1026 + h];
    } else if (tid == 168) sbb = ZX[(size_t)bl*ZXLD + 1024];
    else if (tid == 169) scb = ZX[(size_t)bl*ZXLD + 1025];
    __syncthreads();

    int q = tid;
    if (q < QQ) {
        const float* dp = dist + ((size_t)bl*QQ + q) * 16;
        float d[16];
#pragma unroll
        for (int c = 0; c < 4; c++) {
            float4 v = *(const float4*)(dp + 4*c);
            d[4*c]=v.x; d[4*c+1]=v.y; d[4*c+2]=v.z; d[4*c+3]=v.w;
        }
        float bc0 = 0.f, bc1 = 0.f;
#pragma unroll
        for (int m = 0; m < 16; m++) {
            bc0 = fmaf(d[m], sWbc[m], bc0);
            bc1 = fmaf(d[m], sWbc[16+m], bc1);
        }
        gC[(size_t)bl*320 + q] = bc1 + scb;
        float Bm = bc0 + sbb;
#pragma unroll
        for (int h = 0; h < 8; h++) {
            float dtb = 0.f;
#pragma unroll
            for (int m = 0; m < 16; m++) dtb = fmaf(d[m], sWdt[h*16+m], dtb);
            float dt = fsoftplus(dtb + sdtpb[h] + sdtb[h]);
            size_t base = (((size_t)bl*8 + h)*160 + (q>>1))*4 + (q&1);
            gAT[base]     = fexp(dt * sA[h]);
            gAT[base + 2] = dt * Bm;
        }
    } else if (q < 320) {
        gC[(size_t)bl*320 + q] = 0.f;
#pragma unroll
        for (int h = 0; h < 8; h++) {
            size_t base = (((size_t)bl*8 + h)*160 + (q>>1))*4 + (q&1);
            gAT[base]     = 0.f;
            gAT[base + 2] = 0.f;
        }
    }
}

// 256 blocks = p16(4) x dir(2) x h(8) x b(4); 256 thr = 8 groups x 32 n-lanes, 2 p/thread
// 4-stage cp.async smem ring; 2 CTAs/SM. Stage: [0,2560) AT, [2560,3840) C, [3840,3904) X(16p)
__global__ void __launch_bounds__(256, 2) scan_kernel(
    const float* __restrict__ ZX, const float* __restrict__ Qp,
    const float* __restrict__ gAT, const float* __restrict__ gC,
    const float* __restrict__ Dp,
    float* __restrict__ yf, float* __restrict__ yb,
    float* __restrict__ Sf, float* __restrict__ Sb)
{
    __shared__ __align__(16) unsigned char ring[4][4096];

    int bid = blockIdx.x;
    int pz  = bid & 3;
    int dir = (bid >> 2) & 1;
    int h   = (bid >> 3) & 7;
    int b   = bid >> 6;
    int tid = threadIdx.x;
    int pg  = tid >> 5, nc = tid & 31;
    int p0  = pz*16 + pg*2;
    int n0  = 2*nc;
    float* yout = dir ? yb : yf;
    float* Sout = dir ? Sb : Sf;
    float Dph = Dp[h];
    int bL = b*LL;

    ull S[5][2];
#pragma unroll
    for (int i = 0; i < 5; i++) {
        int n = n0 + 64*i;
        bool v = (n < QQ);
#pragma unroll
        for (int j = 0; j < 2; j++) {
            if (v) S[i][j] = pk(Qp[((size_t)b*QQ + n  )*DI + h*HP + p0 + j],
                                Qp[((size_t)b*QQ + n+1)*DI + h*HP + p0 + j]);
            else   S[i][j] = 0ull;
        }
    }

    int lcur = dir ? (LL-1) : 0;
    int lst  = dir ? -1 : 1;
    int lcur0 = lcur;

    // per-thread cp.async source: base pointer (at l=0 of this (b,h)) + l*stride
    const char* srcBase;
    long srcStride;
    bool doCp = (tid < 244);
    if (tid < 160) {
        srcBase = (const char*)(gAT + ((size_t)bL*8 + h)*640) + tid*16;
        srcStride = 8*640*4;
    } else if (tid < 240) {
        srcBase = (const char*)(gC + (size_t)bL*320) + (tid-160)*16;
        srcStride = 320*4;
    } else {
        srcBase = (const char*)(ZX + (size_t)bL*ZXLD + DI + h*HP + pz*16) + (tid-240)*16;
        srcStride = ZXLD*4;
    }
    unsigned sdst[4];
#pragma unroll
    for (int j = 0; j < 4; j++)
        sdst[j] = (unsigned)__cvta_generic_to_shared(&ring[j][0]) + tid*16;

#define ISSUE(stage, sidx) { \
    int l_ = lcur0 + (sidx)*lst; if (l_ < 0) l_ = 0; if (l_ > LL-1) l_ = LL-1; \
    if (doCp) { \
        const char* s_ = srcBase + (long)l_*srcStride; \
        asm volatile("cp.async.cg.shared.global [%0], [%1], 16;" :: "r"(sdst[stage]), "l"(s_)); \
    } \
    asm volatile("cp.async.commit_group;"); }

    ISSUE(0, 0); ISSUE(1, 1); ISSUE(2, 2);

    // deferred-reduction carries
    float rp0 = 0.f, rp1 = 0.f;
    float xp0 = 0.f, xp1 = 0.f;
    int lprev = lcur;

#define BODY(j, s) { \
    asm volatile("cp.async.wait_group 2;"); \
    __syncthreads(); \
    ISSUE((j+3)&3, (s)+3); \
    const ulonglong2* sAT = (const ulonglong2*)(&ring[j][0]); \
    const ull* sC = (const ull*)(&ring[j][2560]); \
    const float2* sX = (const float2*)(&ring[j][3840]); \
    float2 xq = sX[pg]; \
    ull xb0 = pk(xq.x, xq.x), xb1 = pk(xq.y, xq.y); \
    ull y0 = 0ull, y1 = 0ull; \
    _Pragma("unroll") \
    for (int i = 0; i < 5; i++) { \
        ulonglong2 atv = sAT[nc + 32*i]; \
        ull a = atv.x, t = atv.y, c = sC[nc + 32*i]; \
        S[i][0] = ffma2(S[i][0], a, fmul2(t, xb0)); y0 = ffma2(S[i][0], c, y0); \
        S[i][1] = ffma2(S[i][1], a, fmul2(t, xb1)); y1 = ffma2(S[i][1], c, y1); \
    } \
    float2 f0 = upk(y0), f1 = upk(y1); \
    float t0 = f0.x+f0.y, t1 = f1.x+f1.y; \
    float r0 = rp0, r1 = rp1; \
    _Pragma("unroll") \
    for (int off = 16; off; off >>= 1) { \
        r0 += __shfl_xor_sync(0xffffffffu, r0, off); \
        r1 += __shfl_xor_sync(0xffffffffu, r1, off); \
    } \
    if (nc == 0) { \
        float2 o; \
        o.x = fmaf(Dph, xp0, r0); o.y = fmaf(Dph, xp1, r1); \
        *(float2*)(yout + ((size_t)(bL + lprev)*8 + h)*HP + p0) = o; \
    } \
    rp0 = t0; rp1 = t1; \
    xp0 = xq.x; xp1 = xq.y; \
    lprev = lcur; \
    lcur += lst; }

#pragma unroll 1
    for (int s = 0; s < LL; s += 4) {
        BODY(0, s); BODY(1, s+1); BODY(2, s+2); BODY(3, s+3);
    }

    // final deferred store (step LL-1)
    {
        float r0 = rp0, r1 = rp1;
#pragma unroll
        for (int off = 16; off; off >>= 1) {
            r0 += __shfl_xor_sync(0xffffffffu, r0, off);
            r1 += __shfl_xor_sync(0xffffffffu, r1, off);
        }
        if (nc == 0) {
            float2 o;
            o.x = fmaf(Dph, xp0, r0); o.y = fmaf(Dph, xp1, r1);
            *(float2*)(yout + ((size_t)(bL + lprev)*8 + h)*HP + p0) = o;
        }
    }

    asm volatile("cp.async.wait_group 0;");

#pragma unroll
    for (int i = 0; i < 5; i++) {
        int n = n0 + 64*i;
        if (n < QQ)
#pragma unroll
            for (int j = 0; j < 2; j++) {
                float2 v = upk(S[i][j]);
                *(float2*)(Sout + ((size_t)b*DI + h*HP + p0 + j)*QQ + n) = v;
            }
    }
#undef BODY
#undef ISSUE
}

__global__ void __launch_bounds__(256) keynorm_kernel(
    const float* __restrict__ yf, const float* __restrict__ yb,
    const float* __restrict__ ZX, const float* __restrict__ knw,
    float* __restrict__ keybuf)
{
    int bl = blockIdx.x;
    int t = threadIdx.x;
    float g0, g1;
    {
        float yv = 0.5f*(yf[(size_t)bl*DI + t] + yb[(size_t)bl*DI + t]);
        float zv = ZX[(size_t)bl*ZXLD + t];
        g0 = yv * zv * __fdividef(1.0f, 1.0f + fexp(-zv));
    }
    {
        float yv = 0.5f*(yf[(size_t)bl*DI + t+256] + yb[(size_t)bl*DI + t+256]);
        float zv = ZX[(size_t)bl*ZXLD + t+256];
        g1 = yv * zv * __fdividef(1.0f, 1.0f + fexp(-zv));
    }
    float acc = g0*g0 + g1*g1;
#pragma unroll
    for (int off = 16; off; off >>= 1) acc += __shfl_xor_sync(0xffffffffu, acc, off);
    __shared__ float red[8];
    if ((t & 31) == 0) red[t >> 5] = acc;
    __syncthreads();
    if (t == 0) {
        float s = 0.f;
#pragma unroll
        for (int w = 0; w < 8; w++) s += red[w];
        red[0] = rsqrtf(s * (1.0f/512.0f) + 1e-5f);
    }
    __syncthreads();
    float sc = red[0];
    keybuf[(size_t)bl*DI + t]     = g0 * sc * knw[t];
    keybuf[(size_t)bl*DI + t+256] = g1 * sc * knw[t+256];
}

__global__ void __launch_bounds__(256) querynorm_kernel(
    const float* __restrict__ Sf, const float* __restrict__ Sb,
    const float* __restrict__ lnw, const float* __restrict__ lnb,
    float* __restrict__ lsbuf)
{
    int bq = blockIdx.x;
    int b = bq / QQ, q = bq - b*QQ;
    int t = threadIdx.x;
    float v0 = 0.5f*(Sf[((size_t)b*DI + t)*QQ + q]     + Sb[((size_t)b*DI + t)*QQ + q]);
    float v1 = 0.5f*(Sf[((size_t)b*DI + t+256)*QQ + q] + Sb[((size_t)b*DI + t+256)*QQ + q]);
    float s1 = v0 + v1, s2 = v0*v0 + v1*v1;
#pragma unroll
    for (int off = 16; off; off >>= 1) {
        s1 += __shfl_xor_sync(0xffffffffu, s1, off);
        s2 += __shfl_xor_sync(0xffffffffu, s2, off);
    }
    __shared__ float r1[8], r2[8];
    __shared__ float smu, sinv;
    if ((t & 31) == 0) { r1[t>>5] = s1; r2[t>>5] = s2; }
    __syncthreads();
    if (t == 0) {
        float a = 0.f, c = 0.f;
#pragma unroll
        for (int w = 0; w < 8; w++) { a += r1[w]; c += r2[w]; }
        float mu = a * (1.0f/512.0f);
        smu = mu;
        sinv = rsqrtf(c * (1.0f/512.0f) - mu*mu + 1e-5f);
    }
    __syncthreads();
    float mu = smu, inv = sinv;
    lsbuf[(size_t)bq*DI + t]     = (v0 - mu)*inv*lnw[t]     + lnb[t];
    lsbuf[(size_t)bq*DI + t+256] = (v1 - mu)*inv*lnw[t+256] + lnb[t+256];
}

extern "C" void kernel_launch(void* const* d_in, const int* in_sizes, int n_in,
                              void* d_out, int out_size)
{
    const float* in_key    = (const float*)d_in[0];
    const float* in_query  = (const float*)d_in[1];
    const float* dist      = (const float*)d_in[2];
    const float* W_key     = (const float*)d_in[3];
    const float* W_query   = (const float*)d_in[4];
    const float* W_bc      = (const float*)d_in[5];
    const float* W_dt      = (const float*)d_in[6];
    const float* dt_bias   = (const float*)d_in[7];
    const float* A_log     = (const float*)d_in[8];
    const float* Dp        = (const float*)d_in[9];
    const float* W_out_key = (const float*)d_in[10];
    const float* W_out_qry = (const float*)d_in[11];
    const float* knw       = (const float*)d_in[12];
    const float* lnw       = (const float*)d_in[13];
    const float* lnb       = (const float*)d_in[14];
    float* out = (float*)d_out;

    float *ZX,*Qp,*AT,*C,*yf,*yb,*Sf,*Sb,*key,*ls;
    cudaGetSymbolAddress((void**)&ZX,  g_ZX);
    cudaGetSymbolAddress((void**)&Qp,  g_Qp);
    cudaGetSymbolAddress((void**)&AT,  g_AT);
    cudaGetSymbolAddress((void**)&C,   g_C);
    cudaGetSymbolAddress((void**)&yf,  g_yf);
    cudaGetSymbolAddress((void**)&yb,  g_yb);
    cudaGetSymbolAddress((void**)&Sf,  g_Sf);
    cudaGetSymbolAddress((void**)&Sb,  g_Sb);
    cudaGetSymbolAddress((void**)&key, g_key);
    cudaGetSymbolAddress((void**)&ls,  g_ls);

    gemm_nt<<<dim3((1034+63)/64, (BB*LL)/64), 256>>>(in_key, W_key, ZX, BB*LL, 1034, DM, DM, ZXLD);
    gemm_nt<<<dim3(DI/64, (BB*QQ+63)/64), 256>>>(in_query, W_query, Qp, BB*QQ, DI, DM, DM, DI);
    prepass_kernel<<<BB*LL, 320>>>(dist, ZX, W_bc, W_dt, dt_bias, A_log, AT, C);
    scan_kernel<<<256, 256>>>(ZX, Qp, AT, C, Dp, yf, yb, Sf, Sb);
    keynorm_kernel<<<BB*LL, 256>>>(yf, yb, ZX, knw, key);
    gemm_nt<<<dim3(DM/64, (BB*LL)/64), 256>>>(key, W_out_key, out, BB*LL, DM, DI, DI, DM);
    querynorm_kernel<<<BB*QQ, 256>>>(Sf, Sb, lnw, lnb, ls);
    gemm_nt<<<dim3(DM/64, (BB*QQ+63)/64), 256>>>(ls, W_out_qry, out + (size_t)BB*LL*DM, BB*QQ, DM, DI, DI, DM);
}

// round 13
// speedup vs baseline: 2.1267x; 2.1267x over previous
#include <cuda_runtime.h>
#include <cuda_bf16.h>

#define BB 4
#define LL 2048
#define QQ 300
#define DM 256
#define DI 512
#define NH 8
#define HP 64
#define ZXLD 1040

typedef unsigned long long ull;

__device__ float g_ZX [BB*LL*ZXLD];
__device__ float g_Qp [BB*QQ*DI];
__device__ float g_AT [(size_t)BB*LL*NH*640];   // packed (dA0,dA1,dtB0,dtB1) x 160 pairs, lane-major
__device__ float g_C  [BB*LL*320];              // padded to 320
__device__ float g_yf [BB*LL*DI];
__device__ float g_yb [BB*LL*DI];
__device__ float g_Sf [BB*DI*QQ];
__device__ float g_Sb [BB*DI*QQ];
__device__ float g_key[BB*LL*DI];
__device__ float g_ls [BB*QQ*DI];

__device__ __forceinline__ float fexp(float x) {
    x = fminf(fmaxf(x, -80.0f), 80.0f);
    float t = x * 1.4426950408889634f;
    float n = rintf(t);
    float f = t - n;
    float p = 1.3400886e-3f;
    p = fmaf(p, f, 9.6181291e-3f);
    p = fmaf(p, f, 5.5503633e-2f);
    p = fmaf(p, f, 2.4022646e-1f);
    p = fmaf(p, f, 6.9314718e-1f);
    p = fmaf(p, f, 1.0f);
    return p * __int_as_float(((int)n + 127) << 23);
}

__device__ __forceinline__ float flog(float x) {
    int ix = __float_as_int(x);
    int e = ((ix >> 23) & 255) - 127;
    float m = __int_as_float((ix & 0x007fffff) | 0x3f800000);
    if (m > 1.41421356f) { m *= 0.5f; e += 1; }
    float t = m - 1.0f;
    float p = 7.0376836292e-2f;
    p = fmaf(p, t, -1.1514610310e-1f);
    p = fmaf(p, t,  1.1676998740e-1f);
    p = fmaf(p, t, -1.2420140846e-1f);
    p = fmaf(p, t,  1.4249322787e-1f);
    p = fmaf(p, t, -1.6668057665e-1f);
    p = fmaf(p, t,  2.0000714765e-1f);
    p = fmaf(p, t, -2.4999993993e-1f);
    p = fmaf(p, t,  3.3333331174e-1f);
    float t2 = t * t;
    float r = fmaf(t * t2, p, fmaf(-0.5f, t2, t));
    return fmaf((float)e, 0.6931471805599453f, r);
}

__device__ __forceinline__ float fsoftplus(float x) {
    return fmaxf(x, 0.0f) + flog(1.0f + fexp(-fabsf(x)));
}

__device__ __forceinline__ ull pk(float x, float y) {
    ull r; asm("mov.b64 %0,{%1,%2};" : "=l"(r) : "f"(x), "f"(y)); return r;
}
__device__ __forceinline__ float2 upk(ull v) {
    float2 f; asm("mov.b64 {%0,%1},%2;" : "=f"(f.x), "=f"(f.y) : "l"(v)); return f;
}
__device__ __forceinline__ ull ffma2(ull a, ull b, ull c) {
    ull r; asm("fma.rn.f32x2 %0,%1,%2,%3;" : "=l"(r) : "l"(a), "l"(b), "l"(c)); return r;
}
__device__ __forceinline__ ull fmul2(ull a, ull b) {
    ull r; asm("mul.rn.f32x2 %0,%1,%2;" : "=l"(r) : "l"(a), "l"(b)); return r;
}

// C[M,N] = A[M,K] @ W[N,K]^T
__global__ void __launch_bounds__(256) gemm_nt(
    const float* __restrict__ A, const float* __restrict__ W, float* __restrict__ C,
    int M, int N, int K, int lda, int ldc)
{
    __shared__ __align__(16) float As[16][68];
    __shared__ __align__(16) float Ws[16][68];
    int bm = blockIdx.y * 64, bn = blockIdx.x * 64;
    int tid = threadIdx.x;
    int lm = tid >> 2, lk = (tid & 3) << 2;
    int tm = (tid >> 4) << 2, tn = (tid & 15) << 2;
    float acc[4][4];
#pragma unroll
    for (int i = 0; i < 4; i++)
#pragma unroll
        for (int j = 0; j < 4; j++) acc[i][j] = 0.0f;

    for (int k0 = 0; k0 < K; k0 += 16) {
        float4 av = make_float4(0.f,0.f,0.f,0.f);
        if (bm + lm < M) av = *(const float4*)(A + (size_t)(bm+lm)*lda + k0 + lk);
        As[lk+0][lm]=av.x; As[lk+1][lm]=av.y; As[lk+2][lm]=av.z; As[lk+3][lm]=av.w;
        float4 wv = make_float4(0.f,0.f,0.f,0.f);
        if (bn + lm < N) wv = *(const float4*)(W + (size_t)(bn+lm)*K + k0 + lk);
        Ws[lk+0][lm]=wv.x; Ws[lk+1][lm]=wv.y; Ws[lk+2][lm]=wv.z; Ws[lk+3][lm]=wv.w;
        __syncthreads();
#pragma unroll
        for (int kk = 0; kk < 16; kk++) {
            float4 a = *(const float4*)&As[kk][tm];
            float4 b = *(const float4*)&Ws[kk][tn];
            acc[0][0]=fmaf(a.x,b.x,acc[0][0]); acc[0][1]=fmaf(a.x,b.y,acc[0][1]);
            acc[0][2]=fmaf(a.x,b.z,acc[0][2]); acc[0][3]=fmaf(a.x,b.w,acc[0][3]);
            acc[1][0]=fmaf(a.y,b.x,acc[1][0]); acc[1][1]=fmaf(a.y,b.y,acc[1][1]);
            acc[1][2]=fmaf(a.y,b.z,acc[1][2]); acc[1][3]=fmaf(a.y,b.w,acc[1][3]);
            acc[2][0]=fmaf(a.z,b.x,acc[2][0]); acc[2][1]=fmaf(a.z,b.y,acc[2][1]);
            acc[2][2]=fmaf(a.z,b.z,acc[2][2]); acc[2][3]=fmaf(a.z,b.w,acc[2][3]);
            acc[3][0]=fmaf(a.w,b.x,acc[3][0]); acc[3][1]=fmaf(a.w,b.y,acc[3][1]);
            acc[3][2]=fmaf(a.w,b.z,acc[3][2]); acc[3][3]=fmaf(a.w,b.w,acc[3][3]);
        }
        __syncthreads();
    }
#pragma unroll
    for (int i = 0; i < 4; i++) {
        int row = bm + tm + i;
        if (row < M)
#pragma unroll
            for (int j = 0; j < 4; j++) {
                int col = bn + tn + j;
                if (col < N) C[(size_t)row*ldc + col] = acc[i][j];
            }
    }
}

__global__ void __launch_bounds__(320) prepass_kernel(
    const float* __restrict__ dist, const float* __restrict__ ZX,
    const float* __restrict__ W_bc, const float* __restrict__ W_dt,
    const float* __restrict__ dt_bias, const float* __restrict__ A_log,
    float* __restrict__ gAT, float* __restrict__ gC)
{
    int bl = blockIdx.x;
    int tid = threadIdx.x;
    __shared__ float sWbc[32], sWdt[128], sA[8], sdtb[8], sdtpb[8], sbb, scb;
    if (tid < 32) sWbc[tid] = W_bc[tid];
    else if (tid < 160) sWdt[tid-32] = W_dt[tid-32];
    else if (tid < 168) {
        int h = tid - 160;
        sA[h] = -fexp(A_log[h]);
        sdtb[h] = dt_bias[h];
        sdtpb[h] = ZX[(size_t)bl*ZXLD + 1026 + h];
    } else if (tid == 168) sbb = ZX[(size_t)bl*ZXLD + 1024];
    else if (tid == 169) scb = ZX[(size_t)bl*ZXLD + 1025];
    __syncthreads();

    int q = tid;
    if (q < QQ) {
        const float* dp = dist + ((size_t)bl*QQ + q) * 16;
        float d[16];
#pragma unroll
        for (int c = 0; c < 4; c++) {
            float4 v = *(const float4*)(dp + 4*c);
            d[4*c]=v.x; d[4*c+1]=v.y; d[4*c+2]=v.z; d[4*c+3]=v.w;
        }
        float bc0 = 0.f, bc1 = 0.f;
#pragma unroll
        for (int m = 0; m < 16; m++) {
            bc0 = fmaf(d[m], sWbc[m], bc0);
            bc1 = fmaf(d[m], sWbc[16+m], bc1);
        }
        gC[(size_t)bl*320 + q] = bc1 + scb;
        float Bm = bc0 + sbb;
#pragma unroll
        for (int h = 0; h < 8; h++) {
            float dtb = 0.f;
#pragma unroll
            for (int m = 0; m < 16; m++) dtb = fmaf(d[m], sWdt[h*16+m], dtb);
            float dt = fsoftplus(dtb + sdtpb[h] + sdtb[h]);
            size_t base = (((size_t)bl*8 + h)*160 + (q>>1))*4 + (q&1);
            gAT[base]     = fexp(dt * sA[h]);
            gAT[base + 2] = dt * Bm;
        }
    } else if (q < 320) {
        gC[(size_t)bl*320 + q] = 0.f;
#pragma unroll
        for (int h = 0; h < 8; h++) {
            size_t base = (((size_t)bl*8 + h)*160 + (q>>1))*4 + (q&1);
            gAT[base]     = 0.f;
            gAT[base + 2] = 0.f;
        }
    }
}

// 128 blocks = phalf(2) x dir(2) x h(8) x b(4); 256 thr = 8 p-quads x 32 n-lanes
// 4-stage cp.async smem ring, 2 timesteps per stage (8KB): barrier per 2 steps,
// second step's LDS overlaps first step's FMA. Sub-slot k at +k*4096:
// [0,2560) AT, [2560,3840) C, [3840,3968) X.
__global__ void __launch_bounds__(256, 1) scan_kernel(
    const float* __restrict__ ZX, const float* __restrict__ Qp,
    const float* __restrict__ gAT, const float* __restrict__ gC,
    const float* __restrict__ Dp,
    float* __restrict__ yf, float* __restrict__ yb,
    float* __restrict__ Sf, float* __restrict__ Sb)
{
    __shared__ __align__(16) unsigned char ring[4][8192];

    int bid = blockIdx.x;
    int ph  = bid & 1;
    int dir = (bid >> 1) & 1;
    int h   = (bid >> 2) & 7;
    int b   = bid >> 5;
    int tid = threadIdx.x;
    int pq  = tid >> 5, nc = tid & 31;
    int p0  = ph*32 + pq*4;
    int n0  = 2*nc;
    float* yout = dir ? yb : yf;
    float* Sout = dir ? Sb : Sf;
    float Dph = Dp[h];
    int bL = b*LL;

    ull S[5][4];
#pragma unroll
    for (int i = 0; i < 5; i++) {
        int n = n0 + 64*i;
        bool v = (n < QQ);
#pragma unroll
        for (int j = 0; j < 4; j++) {
            if (v) S[i][j] = pk(Qp[((size_t)b*QQ + n  )*DI + h*HP + p0 + j],
                                Qp[((size_t)b*QQ + n+1)*DI + h*HP + p0 + j]);
            else   S[i][j] = 0ull;
        }
    }

    int lcur = dir ? (LL-1) : 0;
    int lst  = dir ? -1 : 1;
    int lcur0 = lcur;

    const char* srcBase;
    long srcStride;
    bool doCp = (tid < 248);
    if (tid < 160) {
        srcBase = (const char*)(gAT + ((size_t)bL*8 + h)*640) + tid*16;
        srcStride = 8*640*4;
    } else if (tid < 240) {
        srcBase = (const char*)(gC + (size_t)bL*320) + (tid-160)*16;
        srcStride = 320*4;
    } else {
        srcBase = (const char*)(ZX + (size_t)bL*ZXLD + DI + h*HP + ph*32) + (tid-240)*16;
        srcStride = ZXLD*4;
    }
    unsigned sdst[4];
#pragma unroll
    for (int j = 0; j < 4; j++)
        sdst[j] = (unsigned)__cvta_generic_to_shared(&ring[j][0]) + tid*16;

// stage a PAIR of timesteps (pair index pidx -> l = lcur0 + (2*pidx+k)*lst)
#define ISSUE2(stage, pidx) { \
    if (doCp) { \
        int la_ = lcur0 + (2*(pidx)  )*lst; if (la_ < 0) la_ = 0; if (la_ > LL-1) la_ = LL-1; \
        int lb_ = lcur0 + (2*(pidx)+1)*lst; if (lb_ < 0) lb_ = 0; if (lb_ > LL-1) lb_ = LL-1; \
        const char* sa_ = srcBase + (long)la_*srcStride; \
        const char* sb_ = srcBase + (long)lb_*srcStride; \
        asm volatile("cp.async.cg.shared.global [%0], [%1], 16;" :: "r"(sdst[stage]), "l"(sa_)); \
        asm volatile("cp.async.cg.shared.global [%0], [%1], 16;" :: "r"(sdst[stage]+4096u), "l"(sb_)); \
    } \
    asm volatile("cp.async.commit_group;"); }

    ISSUE2(0, 0); ISSUE2(1, 1); ISSUE2(2, 2);

    // deferred-reduction carries
    float rp0 = 0.f, rp1 = 0.f, rp2 = 0.f, rp3 = 0.f;
    float xp0 = 0.f, xp1 = 0.f, xp2 = 0.f, xp3 = 0.f;
    int lprev = lcur;
    int pf = 3;

#define STEPK(j, k) { \
    const ulonglong2* sAT = (const ulonglong2*)(&ring[j][(k)*4096]); \
    const ull* sC = (const ull*)(&ring[j][(k)*4096 + 2560]); \
    const float4* sX = (const float4*)(&ring[j][(k)*4096 + 3840]); \
    float4 xq = sX[pq]; \
    ull xb0 = pk(xq.x, xq.x), xb1 = pk(xq.y, xq.y); \
    ull xb2 = pk(xq.z, xq.z), xb3 = pk(xq.w, xq.w); \
    ull y0 = 0ull, y1 = 0ull, y2 = 0ull, y3 = 0ull; \
    _Pragma("unroll") \
    for (int i = 0; i < 5; i++) { \
        ulonglong2 atv = sAT[nc + 32*i]; \
        ull a = atv.x, t = atv.y, c = sC[nc + 32*i]; \
        S[i][0] = ffma2(S[i][0], a, fmul2(t, xb0)); y0 = ffma2(S[i][0], c, y0); \
        S[i][1] = ffma2(S[i][1], a, fmul2(t, xb1)); y1 = ffma2(S[i][1], c, y1); \
        S[i][2] = ffma2(S[i][2], a, fmul2(t, xb2)); y2 = ffma2(S[i][2], c, y2); \
        S[i][3] = ffma2(S[i][3], a, fmul2(t, xb3)); y3 = ffma2(S[i][3], c, y3); \
    } \
    float2 f0 = upk(y0), f1 = upk(y1), f2 = upk(y2), f3 = upk(y3); \
    float t0 = f0.x+f0.y, t1 = f1.x+f1.y, t2 = f2.x+f2.y, t3 = f3.x+f3.y; \
    float r0 = rp0, r1 = rp1, r2 = rp2, r3 = rp3; \
    _Pragma("unroll") \
    for (int off = 16; off; off >>= 1) { \
        r0 += __shfl_xor_sync(0xffffffffu, r0, off); \
        r1 += __shfl_xor_sync(0xffffffffu, r1, off); \
        r2 += __shfl_xor_sync(0xffffffffu, r2, off); \
        r3 += __shfl_xor_sync(0xffffffffu, r3, off); \
    } \
    if (nc == 0) { \
        float4 o; \
        o.x = fmaf(Dph, xp0, r0); o.y = fmaf(Dph, xp1, r1); \
        o.z = fmaf(Dph, xp2, r2); o.w = fmaf(Dph, xp3, r3); \
        *(float4*)(yout + ((size_t)(bL + lprev)*8 + h)*HP + p0) = o; \
    } \
    rp0 = t0; rp1 = t1; rp2 = t2; rp3 = t3; \
    xp0 = xq.x; xp1 = xq.y; xp2 = xq.z; xp3 = xq.w; \
    lprev = lcur; \
    lcur += lst; }

#define BODY2(j) { \
    asm volatile("cp.async.wait_group 2;"); \
    __syncthreads(); \
    ISSUE2((j+3)&3, pf); pf++; \
    STEPK(j, 0); \
    STEPK(j, 1); }

#pragma unroll 1
    for (int s = 0; s < LL; s += 8) {
        BODY2(0); BODY2(1); BODY2(2); BODY2(3);
    }

    // final deferred store (step LL-1)
    {
        float r0 = rp0, r1 = rp1, r2 = rp2, r3 = rp3;
#pragma unroll
        for (int off = 16; off; off >>= 1) {
            r0 += __shfl_xor_sync(0xffffffffu, r0, off);
            r1 += __shfl_xor_sync(0xffffffffu, r1, off);
            r2 += __shfl_xor_sync(0xffffffffu, r2, off);
            r3 += __shfl_xor_sync(0xffffffffu, r3, off);
        }
        if (nc == 0) {
            float4 o;
            o.x = fmaf(Dph, xp0, r0); o.y = fmaf(Dph, xp1, r1);
            o.z = fmaf(Dph, xp2, r2); o.w = fmaf(Dph, xp3, r3);
            *(float4*)(yout + ((size_t)(bL + lprev)*8 + h)*HP + p0) = o;
        }
    }

    asm volatile("cp.async.wait_group 0;");

#pragma unroll
    for (int i = 0; i < 5; i++) {
        int n = n0 + 64*i;
        if (n < QQ)
#pragma unroll
            for (int j = 0; j < 4; j++) {
                float2 v = upk(S[i][j]);
                *(float2*)(Sout + ((size_t)b*DI + h*HP + p0 + j)*QQ + n) = v;
            }
    }
#undef BODY2
#undef STEPK
#undef ISSUE2
}

__global__ void __launch_bounds__(256) keynorm_kernel(
    const float* __restrict__ yf, const float* __restrict__ yb,
    const float* __restrict__ ZX, const float* __restrict__ knw,
    float* __restrict__ keybuf)
{
    int bl = blockIdx.x;
    int t = threadIdx.x;
    float g0, g1;
    {
        float yv = 0.5f*(yf[(size_t)bl*DI + t] + yb[(size_t)bl*DI + t]);
        float zv = ZX[(size_t)bl*ZXLD + t];
        g0 = yv * zv * __fdividef(1.0f, 1.0f + fexp(-zv));
    }
    {
        float yv = 0.5f*(yf[(size_t)bl*DI + t+256] + yb[(size_t)bl*DI + t+256]);
        float zv = ZX[(size_t)bl*ZXLD + t+256];
        g1 = yv * zv * __fdividef(1.0f, 1.0f + fexp(-zv));
    }
    float acc = g0*g0 + g1*g1;
#pragma unroll
    for (int off = 16; off; off >>= 1) acc += __shfl_xor_sync(0xffffffffu, acc, off);
    __shared__ float red[8];
    if ((t & 31) == 0) red[t >> 5] = acc;
    __syncthreads();
    if (t == 0) {
        float s = 0.f;
#pragma unroll
        for (int w = 0; w < 8; w++) s += red[w];
        red[0] = rsqrtf(s * (1.0f/512.0f) + 1e-5f);
    }
    __syncthreads();
    float sc = red[0];
    keybuf[(size_t)bl*DI + t]     = g0 * sc * knw[t];
    keybuf[(size_t)bl*DI + t+256] = g1 * sc * knw[t+256];
}

__global__ void __launch_bounds__(256) querynorm_kernel(
    const float* __restrict__ Sf, const float* __restrict__ Sb,
    const float* __restrict__ lnw, const float* __restrict__ lnb,
    float* __restrict__ lsbuf)
{
    int bq = blockIdx.x;
    int b = bq / QQ, q = bq - b*QQ;
    int t = threadIdx.x;
    float v0 = 0.5f*(Sf[((size_t)b*DI + t)*QQ + q]     + Sb[((size_t)b*DI + t)*QQ + q]);
    float v1 = 0.5f*(Sf[((size_t)b*DI + t+256)*QQ + q] + Sb[((size_t)b*DI + t+256)*QQ + q]);
    float s1 = v0 + v1, s2 = v0*v0 + v1*v1;
#pragma unroll
    for (int off = 16; off; off >>= 1) {
        s1 += __shfl_xor_sync(0xffffffffu, s1, off);
        s2 += __shfl_xor_sync(0xffffffffu, s2, off);
    }
    __shared__ float r1[8], r2[8];
    __shared__ float smu, sinv;
    if ((t & 31) == 0) { r1[t>>5] = s1; r2[t>>5] = s2; }
    __syncthreads();
    if (t == 0) {
        float a = 0.f, c = 0.f;
#pragma unroll
        for (int w = 0; w < 8; w++) { a += r1[w]; c += r2[w]; }
        float mu = a * (1.0f/512.0f);
        smu = mu;
        sinv = rsqrtf(c * (1.0f/512.0f) - mu*mu + 1e-5f);
    }
    __syncthreads();
    float mu = smu, inv = sinv;
    lsbuf[(size_t)bq*DI + t]     = (v0 - mu)*inv*lnw[t]     + lnb[t];
    lsbuf[(size_t)bq*DI + t+256] = (v1 - mu)*inv*lnw[t+256] + lnb[t+256];
}

extern "C" void kernel_launch(void* const* d_in, const int* in_sizes, int n_in,
                              void* d_out, int out_size)
{
    const float* in_key    = (const float*)d_in[0];
    const float* in_query  = (const float*)d_in[1];
    const float* dist      = (const float*)d_in[2];
    const float* W_key     = (const float*)d_in[3];
    const float* W_query   = (const float*)d_in[4];
    const float* W_bc      = (const float*)d_in[5];
    const float* W_dt      = (const float*)d_in[6];
    const float* dt_bias   = (const float*)d_in[7];
    const float* A_log     = (const float*)d_in[8];
    const float* Dp        = (const float*)d_in[9];
    const float* W_out_key = (const float*)d_in[10];
    const float* W_out_qry = (const float*)d_in[11];
    const float* knw       = (const float*)d_in[12];
    const float* lnw       = (const float*)d_in[13];
    const float* lnb       = (const float*)d_in[14];
    float* out = (float*)d_out;

    float *ZX,*Qp,*AT,*C,*yf,*yb,*Sf,*Sb,*key,*ls;
    cudaGetSymbolAddress((void**)&ZX,  g_ZX);
    cudaGetSymbolAddress((void**)&Qp,  g_Qp);
    cudaGetSymbolAddress((void**)&AT,  g_AT);
    cudaGetSymbolAddress((void**)&C,   g_C);
    cudaGetSymbolAddress((void**)&yf,  g_yf);
    cudaGetSymbolAddress((void**)&yb,  g_yb);
    cudaGetSymbolAddress((void**)&Sf,  g_Sf);
    cudaGetSymbolAddress((void**)&Sb,  g_Sb);
    cudaGetSymbolAddress((void**)&key, g_key);
    cudaGetSymbolAddress((void**)&ls,  g_ls);

    gemm_nt<<<dim3((1034+63)/64, (BB*LL)/64), 256>>>(in_key, W_key, ZX, BB*LL, 1034, DM, DM, ZXLD);
    gemm_nt<<<dim3(DI/64, (BB*QQ+63)/64), 256>>>(in_query, W_query, Qp, BB*QQ, DI, DM, DM, DI);
    prepass_kernel<<<BB*LL, 320>>>(dist, ZX, W_bc, W_dt, dt_bias, A_log, AT, C);
    scan_kernel<<<128, 256>>>(ZX, Qp, AT, C, Dp, yf, yb, Sf, Sb);
    keynorm_kernel<<<BB*LL, 256>>>(yf, yb, ZX, knw, key);
    gemm_nt<<<dim3(DM/64, (BB*LL)/64), 256>>>(key, W_out_key, out, BB*LL, DM, DI, DI, DM);
    querynorm_kernel<<<BB*QQ, 256>>>(Sf, Sb, lnw, lnb, ls);
    gemm_nt<<<dim3(DM/64, (BB*QQ+63)/64), 256>>>(ls, W_out_qry, out + (size_t)BB*LL*DM, BB*QQ, DM, DI, DI, DM);
}